// round 13
// baseline (speedup 1.0000x reference)
#include <cuda_runtime.h>
#include <cuda_fp16.h>
#include <math.h>
#include <stdint.h>

#define NN 50000
#define NE 1000000
#define DF 512
#define FA 64
#define SLOPE 0.2f

#define N4 (NN / 4)            // 12500 int4
#define SBLK 13                // scan blocks: 13 * 1024 int4 >= N4

// ---------------- scratch (device globals) ----------------------------------
__device__ uint2 g_zh[NN * 16];          // z as half2 pairs
__device__ float g_s1[NN];
__device__ float g_s2[NN];
__device__ __align__(16) int g_cnt[NN];      // zero at entry; re-zeroed in cnt_write
__device__ __align__(16) int g_off[NN + 4];
__device__ __align__(16) int g_cur[NN + 4];
__device__ int2  g_se[NE];               // (src, exp(e)) per CSR slot
__device__ int   g_perm[NN];
__device__ int   g_pc[2];
__device__ int   g_nbs[SBLK];
__device__ int   g_cbs[SBLK];
__device__ __align__(16) uint32_t g_wcvt[2 * FA * DF];   // Wd|Wm as tf32
__device__ __align__(16) float g_wv[2048];   // [type][half][512]: W^T @ Wa halves

// ---------------- helpers -----------------------------------------------------
__device__ __forceinline__ uint32_t smem_u32(const void* p) {
    uint32_t a;
    asm("{ .reg .u64 t; cvta.to.shared.u64 t, %1; cvt.u32.u64 %0, t; }" : "=r"(a) : "l"(p));
    return a;
}
__device__ __forceinline__ void cp16(uint32_t dst, const void* src) {
    asm volatile("cp.async.cg.shared.global [%0], [%1], 16;" :: "r"(dst), "l"(src));
}
#define CP_COMMIT() asm volatile("cp.async.commit_group;" ::: "memory")
#define CP_WAIT(n)  asm volatile("cp.async.wait_group %0;" :: "n"(n) : "memory")

__device__ __forceinline__ uint32_t tf32c(float x) {
    uint32_t r;
    asm("cvt.rna.tf32.f32 %0, %1;" : "=r"(r) : "f"(x));
    return r;
}
__device__ __forceinline__ uint32_t pack_h2(float lo, float hi) {
    __half2 h = __floats2half2_rn(lo, hi);
    return *reinterpret_cast<uint32_t*>(&h);
}
__device__ __forceinline__ void mma_tf32(float4& d, uint32_t a0, uint32_t a1,
                                         uint32_t a2, uint32_t a3,
                                         uint32_t b0, uint32_t b1) {
    asm volatile(
        "mma.sync.aligned.m16n8k8.row.col.f32.tf32.tf32.f32 "
        "{%0,%1,%2,%3}, {%4,%5,%6,%7}, {%8,%9}, {%0,%1,%2,%3};"
        : "+f"(d.x), "+f"(d.y), "+f"(d.z), "+f"(d.w)
        : "r"(a0), "r"(a1), "r"(a2), "r"(a3), "r"(b0), "r"(b1));
}

__device__ __forceinline__ int block_exscan(int s, int lane, int wid,
                                            int* ws, int* tot) {
    int x = s;
    #pragma unroll
    for (int o = 1; o < 32; o <<= 1) {
        int tt = __shfl_up_sync(0xffffffffu, x, o);
        if (lane >= o) x += tt;
    }
    if (lane == 31) ws[wid] = x;
    __syncthreads();
    if (wid == 0) {
        int y = ws[lane];
        #pragma unroll
        for (int o = 1; o < 32; o <<= 1) {
            int tt = __shfl_up_sync(0xffffffffu, y, o);
            if (lane >= o) y += tt;
        }
        ws[lane] = y;
    }
    __syncthreads();
    *tot = ws[31];
    return (wid ? ws[wid - 1] : 0) + x - s;
}

// ---------------- K_wcvt: W -> tf32 bits ----------------------------------------
__global__ void k_wcvt(const float* __restrict__ Wd, const float* __restrict__ Wm) {
    int i = blockIdx.x * blockDim.x + threadIdx.x;
    if (i < 2 * FA * DF) {
        float w = (i < FA * DF) ? Wd[i] : Wm[i - FA * DF];
        g_wcvt[i] = tf32c(w);
    }
}

// ---------------- K_watv: v[type][half] = W_type^T @ Wa_half (fp32 exact) ------
__global__ void k_watv(const float* __restrict__ Wd, const float* __restrict__ Wm,
                       const float* __restrict__ Wa) {
    int id = blockIdx.x * blockDim.x + threadIdx.x;
    if (id >= 2048) return;
    int ty = id >> 10;            // 0: type-1 (Wd), 1: type-0 (Wm)
    int h  = (id >> 9) & 1;
    int k  = id & 511;
    const float* W = ty ? Wm : Wd;
    float acc = 0.f;
    #pragma unroll 8
    for (int f = 0; f < FA; ++f)
        acc += Wa[h * FA + f] * W[f * DF + k];
    g_wv[id] = acc;
}

// ---------------- K_score: s1/s2 = x . v (no gemm dependency) -------------------
__global__ void k_score(const float* __restrict__ d_sim,
                        const float* __restrict__ m_sim,
                        const int* __restrict__ nt) {
    int node = (blockIdx.x * blockDim.x + threadIdx.x) >> 5;
    int lane = threadIdx.x & 31;
    if (node >= NN) return;
    int t1 = (nt[node] == 1);
    const float4* x  = (const float4*)((t1 ? d_sim : m_sim) + (size_t)node * DF);
    const float4* wv = (const float4*)(g_wv + (t1 ? 0 : 1024));
    float s1 = 0.f, s2 = 0.f;
    #pragma unroll
    for (int i = 0; i < 4; ++i) {
        float4 xv = x[i * 32 + lane];
        float4 w1 = wv[i * 32 + lane];
        float4 w2 = wv[128 + i * 32 + lane];
        s1 += xv.x * w1.x + xv.y * w1.y + xv.z * w1.z + xv.w * w1.w;
        s2 += xv.x * w2.x + xv.y * w2.y + xv.z * w2.z + xv.w * w2.w;
    }
    #pragma unroll
    for (int o = 16; o; o >>= 1) {
        s1 += __shfl_xor_sync(0xffffffffu, s1, o);
        s2 += __shfl_xor_sync(0xffffffffu, s2, o);
    }
    if (lane == 0) { g_s1[node] = s1; g_s2[node] = s2; }
}

// ---------------- node-type sort: 3-phase parallel scan ------------------------
__global__ __launch_bounds__(1024) void k_nt_bsum(const int* __restrict__ nt) {
    __shared__ int ws[32];
    int idx = blockIdx.x * 1024 + threadIdx.x;
    int4 v = make_int4(0, 0, 0, 0);
    if (idx < N4) v = ((const int4*)nt)[idx];
    int s = v.x + v.y + v.z + v.w;
    int lane = threadIdx.x & 31, wid = threadIdx.x >> 5;
    #pragma unroll
    for (int o = 16; o; o >>= 1) s += __shfl_down_sync(0xffffffffu, s, o);
    if (lane == 0) ws[wid] = s;
    __syncthreads();
    if (wid == 0) {
        int y = ws[lane];
        #pragma unroll
        for (int o = 16; o; o >>= 1) y += __shfl_down_sync(0xffffffffu, y, o);
        if (lane == 0) g_nbs[blockIdx.x] = y;
    }
}

__global__ void k_nt_mid() {
    int lane = threadIdx.x;
    int v = (lane < SBLK) ? g_nbs[lane] : 0;
    int x = v;
    #pragma unroll
    for (int o = 1; o < 32; o <<= 1) {
        int tt = __shfl_up_sync(0xffffffffu, x, o);
        if (lane >= o) x += tt;
    }
    if (lane < SBLK) g_nbs[lane] = x - v;
    if (lane == SBLK - 1) { g_pc[0] = x; g_pc[1] = NN - x; }
}

__global__ __launch_bounds__(1024) void k_nt_write(const int* __restrict__ nt) {
    __shared__ int ws[32];
    int idx = blockIdx.x * 1024 + threadIdx.x;
    int4 v = make_int4(0, 0, 0, 0);
    if (idx < N4) v = ((const int4*)nt)[idx];
    int s = v.x + v.y + v.z + v.w;
    int lane = threadIdx.x & 31, wid = threadIdx.x >> 5;
    int tot;
    int ex = block_exscan(s, lane, wid, ws, &tot);
    if (idx < N4) {
        int p1 = g_nbs[blockIdx.x] + ex;
        int i0 = idx * 4;
        if (v.x) g_perm[p1++] = i0;     else g_perm[NN - 1 - (i0     - p1)] = i0;
        if (v.y) g_perm[p1++] = i0 + 1; else g_perm[NN - 1 - (i0 + 1 - p1)] = i0 + 1;
        if (v.z) g_perm[p1++] = i0 + 2; else g_perm[NN - 1 - (i0 + 2 - p1)] = i0 + 2;
        if (v.w) g_perm[p1++] = i0 + 3; else g_perm[NN - 1 - (i0 + 3 - p1)] = i0 + 3;
    }
}

// ---------------- K_hist ---------------------------------------------------------
__global__ void k_hist(const int* __restrict__ dst) {
    int i = blockIdx.x * blockDim.x + threadIdx.x;
    if (i < NE / 4) {
        int4 d = ((const int4*)dst)[i];
        atomicAdd(&g_cnt[d.x], 1);
        atomicAdd(&g_cnt[d.y], 1);
        atomicAdd(&g_cnt[d.z], 1);
        atomicAdd(&g_cnt[d.w], 1);
    }
}

// ---------------- cnt scan: 3-phase ---------------------------------------------
__global__ __launch_bounds__(1024) void k_cnt_bsum() {
    __shared__ int ws[32];
    int idx = blockIdx.x * 1024 + threadIdx.x;
    int4 v = make_int4(0, 0, 0, 0);
    if (idx < N4) v = ((const int4*)g_cnt)[idx];
    int s = v.x + v.y + v.z + v.w;
    int lane = threadIdx.x & 31, wid = threadIdx.x >> 5;
    #pragma unroll
    for (int o = 16; o; o >>= 1) s += __shfl_down_sync(0xffffffffu, s, o);
    if (lane == 0) ws[wid] = s;
    __syncthreads();
    if (wid == 0) {
        int y = ws[lane];
        #pragma unroll
        for (int o = 16; o; o >>= 1) y += __shfl_down_sync(0xffffffffu, y, o);
        if (lane == 0) g_cbs[blockIdx.x] = y;
    }
}

__global__ void k_cnt_mid() {
    int lane = threadIdx.x;
    int v = (lane < SBLK) ? g_cbs[lane] : 0;
    int x = v;
    #pragma unroll
    for (int o = 1; o < 32; o <<= 1) {
        int tt = __shfl_up_sync(0xffffffffu, x, o);
        if (lane >= o) x += tt;
    }
    if (lane < SBLK) g_cbs[lane] = x - v;
}

__global__ __launch_bounds__(1024) void k_cnt_write() {
    __shared__ int ws[32];
    int idx = blockIdx.x * 1024 + threadIdx.x;
    int4* cnt4 = (int4*)g_cnt;
    int4 v = make_int4(0, 0, 0, 0);
    if (idx < N4) v = cnt4[idx];
    int s = v.x + v.y + v.z + v.w;
    int lane = threadIdx.x & 31, wid = threadIdx.x >> 5;
    int tot;
    int ex = block_exscan(s, lane, wid, ws, &tot);
    if (idx < N4) {
        int excl = g_cbs[blockIdx.x] + ex;
        int4 o;
        o.x = excl;
        o.y = excl + v.x;
        o.z = o.y + v.y;
        o.w = o.z + v.z;
        ((int4*)g_off)[idx] = o;
        ((int4*)g_cur)[idx] = o;
        cnt4[idx] = make_int4(0, 0, 0, 0);
    }
    if (blockIdx.x == 0 && threadIdx.x == 0) g_off[NN] = NE;
}

// ---------------- K2: tf32 mma.sync GEMM (128x64, KC=32, double buffer) --------
#define KC 32
#define PAD 36
#define A_FLOATS (128 * PAD)
#define B_FLOATS (64 * PAD)
#define SMEM_FLOATS (2 * A_FLOATS + 2 * B_FLOATS)
#define NCHUNK (DF / KC)

__global__ __launch_bounds__(256) void k_gemm_mma(
    const float* __restrict__ d_sim, const float* __restrict__ m_sim)
{
    extern __shared__ float dsm[];
    __shared__ int ns[128];

    const int tid  = threadIdx.x;
    const int wid  = tid >> 5;
    const int lane = tid & 31;
    const int g    = lane >> 2;
    const int t    = lane & 3;

    const int c1 = g_pc[0];
    const int tiles_d = (c1 + 127) >> 7;
    const int b = blockIdx.x;

    const float* X; const uint32_t* W; int off, cnt;
    if (b < tiles_d) {
        X = d_sim; W = g_wcvt; off = b * 128; cnt = min(128, c1 - b * 128);
    } else {
        int c0 = NN - c1;
        int b2 = b - tiles_d;
        cnt = min(128, c0 - b2 * 128);
        if (cnt <= 0) return;
        X = m_sim; W = g_wcvt + FA * DF; off = c1 + b2 * 128;
    }

    if (tid < 128) ns[tid] = g_perm[off + min(tid, cnt - 1)];
    __syncthreads();

    const uint32_t smb = smem_u32(dsm);

    auto load_chunk = [&](int buf, int kt) {
        uint32_t bA = smb + buf * A_FLOATS * 4;
        uint32_t bB = smb + (2 * A_FLOATS + buf * B_FLOATS) * 4;
        #pragma unroll
        for (int i = 0; i < 4; ++i) {
            int s = i * 256 + tid;
            int row = s >> 3, q = s & 7;
            cp16(bA + (row * PAD + q * 4) * 4, X + (size_t)ns[row] * DF + kt + q * 4);
        }
        #pragma unroll
        for (int i = 0; i < 2; ++i) {
            int s = i * 256 + tid;
            int row = s >> 3, q = s & 7;
            cp16(bB + (row * PAD + q * 4) * 4, W + (size_t)row * DF + kt + q * 4);
        }
    };

    float4 acc[8];
    #pragma unroll
    for (int j = 0; j < 8; ++j) acc[j] = make_float4(0.f, 0.f, 0.f, 0.f);

    load_chunk(0, 0);
    CP_COMMIT();

    const int m0 = wid * 16;
    for (int c = 0; c < NCHUNK; ++c) {
        if (c + 1 < NCHUNK) {
            load_chunk((c + 1) & 1, (c + 1) * KC);
            CP_COMMIT();
            CP_WAIT(1);
        } else {
            CP_WAIT(0);
        }
        __syncthreads();

        const float*    As = dsm + (c & 1) * A_FLOATS;
        const uint32_t* Bs = (const uint32_t*)(dsm + 2 * A_FLOATS + (c & 1) * B_FLOATS);

        #pragma unroll
        for (int ks = 0; ks < 4; ++ks) {
            const int k0 = ks * 8;
            uint32_t a0 = tf32c(As[(m0 + g)     * PAD + k0 + t]);
            uint32_t a1 = tf32c(As[(m0 + g + 8) * PAD + k0 + t]);
            uint32_t a2 = tf32c(As[(m0 + g)     * PAD + k0 + t + 4]);
            uint32_t a3 = tf32c(As[(m0 + g + 8) * PAD + k0 + t + 4]);
            #pragma unroll
            for (int j = 0; j < 8; ++j) {
                uint32_t b0 = Bs[(8 * j + g) * PAD + k0 + t];
                uint32_t b1 = Bs[(8 * j + g) * PAD + k0 + t + 4];
                mma_tf32(acc[j], a0, a1, a2, a3, b0, b1);
            }
        }
        __syncthreads();
    }

    // ---- epilogue: z rows as half2 (s1/s2 now computed by k_score) ------------
    const int r0 = m0 + g;
    const int r1 = r0 + 8;
    const bool v0 = r0 < cnt, v1 = r1 < cnt;
    int node0 = ns[r0];
    int node1 = ns[r1];
    uint32_t* z0 = (uint32_t*)g_zh + (size_t)node0 * 32;
    uint32_t* z1 = (uint32_t*)g_zh + (size_t)node1 * 32;
    #pragma unroll
    for (int j = 0; j < 8; ++j) {
        if (v0) z0[4 * j + t] = pack_h2(acc[j].x, acc[j].y);
        if (v1) z1[4 * j + t] = pack_h2(acc[j].z, acc[j].w);
    }
}

// ---------------- K_scatter: CSR scatter, 2 edges/thread ----------------------
__global__ void k_scatter(const int* __restrict__ src, const int* __restrict__ dst) {
    int i = blockIdx.x * blockDim.x + threadIdx.x;
    if (i >= NE / 2) return;
    int2 ss = ((const int2*)src)[i];
    int2 dd = ((const int2*)dst)[i];
    {
        float e = g_s1[ss.x] + g_s2[dd.x];
        e = (e > 0.f) ? e : SLOPE * e;
        int p = atomicAdd(&g_cur[dd.x], 1);
        g_se[p] = make_int2(ss.x, __float_as_int(__expf(e)));
    }
    {
        float e = g_s1[ss.y] + g_s2[dd.y];
        e = (e > 0.f) ? e : SLOPE * e;
        int p = atomicAdd(&g_cur[dd.y], 1);
        g_se[p] = make_int2(ss.y, __float_as_int(__expf(e)));
    }
}

// ---------------- K_agg: softmax aggregation + elu ----------------------------
__global__ void k_agg(float* __restrict__ out) {
    int node = (blockIdx.x * blockDim.x + threadIdx.x) >> 5;
    int lane = threadIdx.x & 31;
    if (node >= NN) return;
    int beg = g_off[node], end = g_off[node + 1];
    int q  = lane >> 3;
    int fl = lane & 7;

    float acc[8] = {0.f, 0.f, 0.f, 0.f, 0.f, 0.f, 0.f, 0.f};
    float den = 0.f;
    for (int j = beg + q; j < end; j += 4) {
        int2 se = g_se[j];
        float ex = __int_as_float(se.y);
        uint4 zz = ((const uint4*)g_zh)[(size_t)se.x * 8 + fl];
        float2 f0 = __half22float2(*reinterpret_cast<__half2*>(&zz.x));
        float2 f1 = __half22float2(*reinterpret_cast<__half2*>(&zz.y));
        float2 f2 = __half22float2(*reinterpret_cast<__half2*>(&zz.z));
        float2 f3 = __half22float2(*reinterpret_cast<__half2*>(&zz.w));
        acc[0] += ex * f0.x; acc[1] += ex * f0.y;
        acc[2] += ex * f1.x; acc[3] += ex * f1.y;
        acc[4] += ex * f2.x; acc[5] += ex * f2.y;
        acc[6] += ex * f3.x; acc[7] += ex * f3.y;
        den += ex;
    }
    #pragma unroll
    for (int msk = 8; msk <= 16; msk <<= 1) {
        #pragma unroll
        for (int k = 0; k < 8; ++k)
            acc[k] += __shfl_xor_sync(0xffffffffu, acc[k], msk);
        den += __shfl_xor_sync(0xffffffffu, den, msk);
    }
    if (q == 0) {
        float inv = (end > beg) ? 1.f / den : 0.f;
        #pragma unroll
        for (int k = 0; k < 8; ++k) {
            float v = acc[k] * inv;
            acc[k] = (v > 0.f) ? v : expm1f(v);
        }
        float* orow = out + (size_t)node * FA + fl * 8;
        *(float4*)(orow)     = make_float4(acc[0], acc[1], acc[2], acc[3]);
        *(float4*)(orow + 4) = make_float4(acc[4], acc[5], acc[6], acc[7]);
    }
}

// ---------------- launcher -------------------------------------------------------
extern "C" void kernel_launch(void* const* d_in, const int* in_sizes, int n_in,
                              void* d_out, int out_size) {
    const float* d_sim     = (const float*)d_in[0];
    const float* m_sim     = (const float*)d_in[1];
    const float* Wd        = (const float*)d_in[2];
    const float* Wm        = (const float*)d_in[3];
    const float* Wa        = (const float*)d_in[4];
    const int*   node_type = (const int*)d_in[5];
    const int*   edge_src  = (const int*)d_in[6];
    const int*   edge_dst  = (const int*)d_in[7];
    float* out = (float*)d_out;

    static cudaStream_t s2 = nullptr, s3 = nullptr;
    static cudaEvent_t evFork = nullptr, evW = nullptr, evScore = nullptr,
                       evScat = nullptr;
    if (!s2) {
        cudaStreamCreateWithFlags(&s2, cudaStreamNonBlocking);
        cudaStreamCreateWithFlags(&s3, cudaStreamNonBlocking);
        cudaEventCreateWithFlags(&evFork,  cudaEventDisableTiming);
        cudaEventCreateWithFlags(&evW,     cudaEventDisableTiming);
        cudaEventCreateWithFlags(&evScore, cudaEventDisableTiming);
        cudaEventCreateWithFlags(&evScat,  cudaEventDisableTiming);
        cudaFuncSetAttribute(k_gemm_mma, cudaFuncAttributeMaxDynamicSharedMemorySize,
                             SMEM_FLOATS * 4);
    }

    const int gemm_blocks = (NN + 127) / 128 + 1;

    cudaEventRecord(evFork, 0);
    cudaStreamWaitEvent(s2, evFork, 0);

    // stream0 (node side): W converts -> sort -> GEMM
    k_wcvt     <<<(2 * FA * DF + 255) / 256, 256>>>(Wd, Wm);
    k_watv     <<<8, 256>>>(Wd, Wm, Wa);
    cudaEventRecord(evW, 0);
    cudaStreamWaitEvent(s3, evW, 0);

    k_nt_bsum  <<<SBLK, 1024>>>(node_type);
    k_nt_mid   <<<1, 32>>>();
    k_nt_write <<<SBLK, 1024>>>(node_type);

    // s3: per-node attention scalars (independent of gemm)
    k_score    <<<(NN * 32 + 255) / 256, 256, 0, s3>>>(d_sim, m_sim, node_type);
    cudaEventRecord(evScore, s3);

    // s2: edge histogram + CSR offsets, then scatter once scores land
    k_hist     <<<(NE / 4 + 255) / 256, 256, 0, s2>>>(edge_dst);
    k_cnt_bsum <<<SBLK, 1024, 0, s2>>>();
    k_cnt_mid  <<<1, 32, 0, s2>>>();
    k_cnt_write<<<SBLK, 1024, 0, s2>>>();
    cudaStreamWaitEvent(s2, evScore, 0);
    k_scatter  <<<(NE / 2 + 255) / 256, 256, 0, s2>>>(edge_src, edge_dst);
    cudaEventRecord(evScat, s2);

    k_gemm_mma <<<gemm_blocks, 256, SMEM_FLOATS * 4>>>(d_sim, m_sim);

    cudaStreamWaitEvent(0, evScat, 0);
    k_agg      <<<(NN * 32 + 255) / 256, 256>>>(out);
}

// round 15
// speedup vs baseline: 1.2078x; 1.2078x over previous
#include <cuda_runtime.h>
#include <cuda_fp16.h>
#include <math.h>
#include <stdint.h>

#define NN 50000
#define NE 1000000
#define DF 512
#define FA 64
#define SLOPE 0.2f

#define N4 (NN / 4)
#define SBLK 13

// ---------------- scratch (device globals) ----------------------------------
__device__ uint2 g_zh[NN * 16];          // z as half2 pairs
__device__ float g_s1[NN];
__device__ float g_s2[NN];
__device__ __align__(16) int g_cnt[NN];      // zero at entry; re-zeroed in cnt_write
__device__ __align__(16) int g_off[NN + 4];
__device__ __align__(16) int g_cur[NN + 4];
__device__ int   g_srcs[NE];             // src per CSR slot (no score dependency)
__device__ int   g_perm[NN];
__device__ int   g_pc[2];
__device__ int   g_nbs[SBLK];
__device__ int   g_cbs[SBLK];
__device__ __align__(16) uint32_t g_wcvt[2 * FA * DF];

// ---------------- helpers -----------------------------------------------------
__device__ __forceinline__ uint32_t smem_u32(const void* p) {
    uint32_t a;
    asm("{ .reg .u64 t; cvta.to.shared.u64 t, %1; cvt.u32.u64 %0, t; }" : "=r"(a) : "l"(p));
    return a;
}
__device__ __forceinline__ void cp16(uint32_t dst, const void* src) {
    asm volatile("cp.async.cg.shared.global [%0], [%1], 16;" :: "r"(dst), "l"(src));
}
#define CP_COMMIT() asm volatile("cp.async.commit_group;" ::: "memory")
#define CP_WAIT(n)  asm volatile("cp.async.wait_group %0;" :: "n"(n) : "memory")

__device__ __forceinline__ uint32_t tf32c(float x) {
    uint32_t r;
    asm("cvt.rna.tf32.f32 %0, %1;" : "=r"(r) : "f"(x));
    return r;
}
__device__ __forceinline__ uint32_t pack_h2(float lo, float hi) {
    __half2 h = __floats2half2_rn(lo, hi);
    return *reinterpret_cast<uint32_t*>(&h);
}
__device__ __forceinline__ void mma_tf32(float4& d, uint32_t a0, uint32_t a1,
                                         uint32_t a2, uint32_t a3,
                                         uint32_t b0, uint32_t b1) {
    asm volatile(
        "mma.sync.aligned.m16n8k8.row.col.f32.tf32.tf32.f32 "
        "{%0,%1,%2,%3}, {%4,%5,%6,%7}, {%8,%9}, {%0,%1,%2,%3};"
        : "+f"(d.x), "+f"(d.y), "+f"(d.z), "+f"(d.w)
        : "r"(a0), "r"(a1), "r"(a2), "r"(a3), "r"(b0), "r"(b1));
}

__device__ __forceinline__ int block_exscan(int s, int lane, int wid,
                                            int* ws, int* tot) {
    int x = s;
    #pragma unroll
    for (int o = 1; o < 32; o <<= 1) {
        int tt = __shfl_up_sync(0xffffffffu, x, o);
        if (lane >= o) x += tt;
    }
    if (lane == 31) ws[wid] = x;
    __syncthreads();
    if (wid == 0) {
        int y = ws[lane];
        #pragma unroll
        for (int o = 1; o < 32; o <<= 1) {
            int tt = __shfl_up_sync(0xffffffffu, y, o);
            if (lane >= o) y += tt;
        }
        ws[lane] = y;
    }
    __syncthreads();
    *tot = ws[31];
    return (wid ? ws[wid - 1] : 0) + x - s;
}

// ---------------- K_wcvt --------------------------------------------------------
__global__ void k_wcvt(const float* __restrict__ Wd, const float* __restrict__ Wm) {
    int i = blockIdx.x * blockDim.x + threadIdx.x;
    if (i < 2 * FA * DF) {
        float w = (i < FA * DF) ? Wd[i] : Wm[i - FA * DF];
        g_wcvt[i] = tf32c(w);
    }
}

// ---------------- node-type sort: 3-phase parallel scan ------------------------
__global__ __launch_bounds__(1024) void k_nt_bsum(const int* __restrict__ nt) {
    __shared__ int ws[32];
    int idx = blockIdx.x * 1024 + threadIdx.x;
    int4 v = make_int4(0, 0, 0, 0);
    if (idx < N4) v = ((const int4*)nt)[idx];
    int s = v.x + v.y + v.z + v.w;
    int lane = threadIdx.x & 31, wid = threadIdx.x >> 5;
    #pragma unroll
    for (int o = 16; o; o >>= 1) s += __shfl_down_sync(0xffffffffu, s, o);
    if (lane == 0) ws[wid] = s;
    __syncthreads();
    if (wid == 0) {
        int y = ws[lane];
        #pragma unroll
        for (int o = 16; o; o >>= 1) y += __shfl_down_sync(0xffffffffu, y, o);
        if (lane == 0) g_nbs[blockIdx.x] = y;
    }
}

__global__ void k_nt_mid() {
    int lane = threadIdx.x;
    int v = (lane < SBLK) ? g_nbs[lane] : 0;
    int x = v;
    #pragma unroll
    for (int o = 1; o < 32; o <<= 1) {
        int tt = __shfl_up_sync(0xffffffffu, x, o);
        if (lane >= o) x += tt;
    }
    if (lane < SBLK) g_nbs[lane] = x - v;
    if (lane == SBLK - 1) { g_pc[0] = x; g_pc[1] = NN - x; }
}

__global__ __launch_bounds__(1024) void k_nt_write(const int* __restrict__ nt) {
    __shared__ int ws[32];
    int idx = blockIdx.x * 1024 + threadIdx.x;
    int4 v = make_int4(0, 0, 0, 0);
    if (idx < N4) v = ((const int4*)nt)[idx];
    int s = v.x + v.y + v.z + v.w;
    int lane = threadIdx.x & 31, wid = threadIdx.x >> 5;
    int tot;
    int ex = block_exscan(s, lane, wid, ws, &tot);
    if (idx < N4) {
        int p1 = g_nbs[blockIdx.x] + ex;
        int i0 = idx * 4;
        if (v.x) g_perm[p1++] = i0;     else g_perm[NN - 1 - (i0     - p1)] = i0;
        if (v.y) g_perm[p1++] = i0 + 1; else g_perm[NN - 1 - (i0 + 1 - p1)] = i0 + 1;
        if (v.z) g_perm[p1++] = i0 + 2; else g_perm[NN - 1 - (i0 + 2 - p1)] = i0 + 2;
        if (v.w) g_perm[p1++] = i0 + 3; else g_perm[NN - 1 - (i0 + 3 - p1)] = i0 + 3;
    }
}

// ---------------- K_hist ---------------------------------------------------------
__global__ void k_hist(const int* __restrict__ dst) {
    int i = blockIdx.x * blockDim.x + threadIdx.x;
    if (i < NE / 4) {
        int4 d = ((const int4*)dst)[i];
        atomicAdd(&g_cnt[d.x], 1);
        atomicAdd(&g_cnt[d.y], 1);
        atomicAdd(&g_cnt[d.z], 1);
        atomicAdd(&g_cnt[d.w], 1);
    }
}

// ---------------- cnt scan: 3-phase ---------------------------------------------
__global__ __launch_bounds__(1024) void k_cnt_bsum() {
    __shared__ int ws[32];
    int idx = blockIdx.x * 1024 + threadIdx.x;
    int4 v = make_int4(0, 0, 0, 0);
    if (idx < N4) v = ((const int4*)g_cnt)[idx];
    int s = v.x + v.y + v.z + v.w;
    int lane = threadIdx.x & 31, wid = threadIdx.x >> 5;
    #pragma unroll
    for (int o = 16; o; o >>= 1) s += __shfl_down_sync(0xffffffffu, s, o);
    if (lane == 0) ws[wid] = s;
    __syncthreads();
    if (wid == 0) {
        int y = ws[lane];
        #pragma unroll
        for (int o = 16; o; o >>= 1) y += __shfl_down_sync(0xffffffffu, y, o);
        if (lane == 0) g_cbs[blockIdx.x] = y;
    }
}

__global__ void k_cnt_mid() {
    int lane = threadIdx.x;
    int v = (lane < SBLK) ? g_cbs[lane] : 0;
    int x = v;
    #pragma unroll
    for (int o = 1; o < 32; o <<= 1) {
        int tt = __shfl_up_sync(0xffffffffu, x, o);
        if (lane >= o) x += tt;
    }
    if (lane < SBLK) g_cbs[lane] = x - v;
}

__global__ __launch_bounds__(1024) void k_cnt_write() {
    __shared__ int ws[32];
    int idx = blockIdx.x * 1024 + threadIdx.x;
    int4* cnt4 = (int4*)g_cnt;
    int4 v = make_int4(0, 0, 0, 0);
    if (idx < N4) v = cnt4[idx];
    int s = v.x + v.y + v.z + v.w;
    int lane = threadIdx.x & 31, wid = threadIdx.x >> 5;
    int tot;
    int ex = block_exscan(s, lane, wid, ws, &tot);
    if (idx < N4) {
        int excl = g_cbs[blockIdx.x] + ex;
        int4 o;
        o.x = excl;
        o.y = excl + v.x;
        o.z = o.y + v.y;
        o.w = o.z + v.z;
        ((int4*)g_off)[idx] = o;
        ((int4*)g_cur)[idx] = o;
        cnt4[idx] = make_int4(0, 0, 0, 0);
    }
    if (blockIdx.x == 0 && threadIdx.x == 0) g_off[NN] = NE;
}

// ---------------- K2: tf32 mma.sync GEMM (fused s1/s2 epilogue) ----------------
#define KC 32
#define PAD 36
#define A_FLOATS (128 * PAD)
#define B_FLOATS (64 * PAD)
#define SMEM_FLOATS (2 * A_FLOATS + 2 * B_FLOATS)
#define NCHUNK (DF / KC)

__global__ __launch_bounds__(256) void k_gemm_mma(
    const float* __restrict__ d_sim, const float* __restrict__ m_sim,
    const float* __restrict__ Wa)
{
    extern __shared__ float dsm[];
    __shared__ int ns[128];

    const int tid  = threadIdx.x;
    const int wid  = tid >> 5;
    const int lane = tid & 31;
    const int g    = lane >> 2;
    const int t    = lane & 3;

    const int c1 = g_pc[0];
    const int tiles_d = (c1 + 127) >> 7;
    const int b = blockIdx.x;

    const float* X; const uint32_t* W; int off, cnt;
    if (b < tiles_d) {
        X = d_sim; W = g_wcvt; off = b * 128; cnt = min(128, c1 - b * 128);
    } else {
        int c0 = NN - c1;
        int b2 = b - tiles_d;
        cnt = min(128, c0 - b2 * 128);
        if (cnt <= 0) return;
        X = m_sim; W = g_wcvt + FA * DF; off = c1 + b2 * 128;
    }

    if (tid < 128) ns[tid] = g_perm[off + min(tid, cnt - 1)];
    __syncthreads();

    const uint32_t smb = smem_u32(dsm);

    auto load_chunk = [&](int buf, int kt) {
        uint32_t bA = smb + buf * A_FLOATS * 4;
        uint32_t bB = smb + (2 * A_FLOATS + buf * B_FLOATS) * 4;
        #pragma unroll
        for (int i = 0; i < 4; ++i) {
            int s = i * 256 + tid;
            int row = s >> 3, q = s & 7;
            cp16(bA + (row * PAD + q * 4) * 4, X + (size_t)ns[row] * DF + kt + q * 4);
        }
        #pragma unroll
        for (int i = 0; i < 2; ++i) {
            int s = i * 256 + tid;
            int row = s >> 3, q = s & 7;
            cp16(bB + (row * PAD + q * 4) * 4, W + (size_t)row * DF + kt + q * 4);
        }
    };

    float4 acc[8];
    #pragma unroll
    for (int j = 0; j < 8; ++j) acc[j] = make_float4(0.f, 0.f, 0.f, 0.f);

    load_chunk(0, 0);
    CP_COMMIT();

    const int m0 = wid * 16;
    for (int c = 0; c < NCHUNK; ++c) {
        if (c + 1 < NCHUNK) {
            load_chunk((c + 1) & 1, (c + 1) * KC);
            CP_COMMIT();
            CP_WAIT(1);
        } else {
            CP_WAIT(0);
        }
        __syncthreads();

        const float*    As = dsm + (c & 1) * A_FLOATS;
        const uint32_t* Bs = (const uint32_t*)(dsm + 2 * A_FLOATS + (c & 1) * B_FLOATS);

        #pragma unroll
        for (int ks = 0; ks < 4; ++ks) {
            const int k0 = ks * 8;
            uint32_t a0 = tf32c(As[(m0 + g)     * PAD + k0 + t]);
            uint32_t a1 = tf32c(As[(m0 + g + 8) * PAD + k0 + t]);
            uint32_t a2 = tf32c(As[(m0 + g)     * PAD + k0 + t + 4]);
            uint32_t a3 = tf32c(As[(m0 + g + 8) * PAD + k0 + t + 4]);
            #pragma unroll
            for (int j = 0; j < 8; ++j) {
                uint32_t b0 = Bs[(8 * j + g) * PAD + k0 + t];
                uint32_t b1 = Bs[(8 * j + g) * PAD + k0 + t + 4];
                mma_tf32(acc[j], a0, a1, a2, a3, b0, b1);
            }
        }
        __syncthreads();
    }

    // ---- epilogue: z rows as half2 + fused s1/s2 ------------------------------
    const int r0 = m0 + g;
    const int r1 = r0 + 8;
    const bool v0 = r0 < cnt, v1 = r1 < cnt;
    float s1a = 0.f, s2a = 0.f, s1b = 0.f, s2b = 0.f;
    int node0 = ns[r0];
    int node1 = ns[r1];
    uint32_t* z0 = (uint32_t*)g_zh + (size_t)node0 * 32;
    uint32_t* z1 = (uint32_t*)g_zh + (size_t)node1 * 32;
    #pragma unroll
    for (int j = 0; j < 8; ++j) {
        int n0 = 8 * j + 2 * t;
        float wa1x = Wa[n0], wa1y = Wa[n0 + 1];
        float wa2x = Wa[FA + n0], wa2y = Wa[FA + n0 + 1];
        if (v0) z0[4 * j + t] = pack_h2(acc[j].x, acc[j].y);
        s1a += acc[j].x * wa1x + acc[j].y * wa1y;
        s2a += acc[j].x * wa2x + acc[j].y * wa2y;
        if (v1) z1[4 * j + t] = pack_h2(acc[j].z, acc[j].w);
        s1b += acc[j].z * wa1x + acc[j].w * wa1y;
        s2b += acc[j].z * wa2x + acc[j].w * wa2y;
    }
    #pragma unroll
    for (int msk = 1; msk <= 2; msk <<= 1) {
        s1a += __shfl_xor_sync(0xffffffffu, s1a, msk);
        s2a += __shfl_xor_sync(0xffffffffu, s2a, msk);
        s1b += __shfl_xor_sync(0xffffffffu, s1b, msk);
        s2b += __shfl_xor_sync(0xffffffffu, s2b, msk);
    }
    if (t == 0) {
        if (v0) { g_s1[node0] = s1a; g_s2[node0] = s2a; }
        if (v1) { g_s1[node1] = s1b; g_s2[node1] = s2b; }
    }
}

// ---------------- K_scatter: src-only CSR scatter (NO score dependency) --------
__global__ void k_scatter(const int* __restrict__ src, const int* __restrict__ dst) {
    int i = blockIdx.x * blockDim.x + threadIdx.x;
    if (i >= NE / 2) return;
    int2 ss = ((const int2*)src)[i];
    int2 dd = ((const int2*)dst)[i];
    g_srcs[atomicAdd(&g_cur[dd.x], 1)] = ss.x;
    g_srcs[atomicAdd(&g_cur[dd.y], 1)] = ss.y;
}

// ---------------- K_agg: inline edge logits + softmax aggregation + elu --------
// WARP-UNIFORM loop (all 32 lanes iterate the same count) so the intra-loop
// __shfl_sync is always executed by every lane — the R14 divergence bug fix.
__global__ void k_agg(float* __restrict__ out) {
    int node = (blockIdx.x * blockDim.x + threadIdx.x) >> 5;
    int lane = threadIdx.x & 31;
    if (node >= NN) return;
    int beg = g_off[node], end = g_off[node + 1];
    int q  = lane >> 3;
    int fl = lane & 7;
    float s2n = g_s2[node];

    float acc[8] = {0.f, 0.f, 0.f, 0.f, 0.f, 0.f, 0.f, 0.f};
    float den = 0.f;
    for (int base = beg; base < end; base += 4) {    // uniform across the warp
        int j = base + q;
        bool valid = j < end;
        int s = g_srcs[valid ? j : beg];             // beg valid whenever loop entered
        float ex = 0.f;
        if (fl == 0 && valid) {
            float e = g_s1[s] + s2n;
            e = (e > 0.f) ? e : SLOPE * e;
            ex = __expf(e);
        }
        ex = __shfl_sync(0xffffffffu, ex, lane & 24);   // leader -> group; all lanes present
        uint4 zz = ((const uint4*)g_zh)[(size_t)s * 8 + fl];
        float2 f0 = __half22float2(*reinterpret_cast<__half2*>(&zz.x));
        float2 f1 = __half22float2(*reinterpret_cast<__half2*>(&zz.y));
        float2 f2 = __half22float2(*reinterpret_cast<__half2*>(&zz.z));
        float2 f3 = __half22float2(*reinterpret_cast<__half2*>(&zz.w));
        acc[0] += ex * f0.x; acc[1] += ex * f0.y;
        acc[2] += ex * f1.x; acc[3] += ex * f1.y;
        acc[4] += ex * f2.x; acc[5] += ex * f2.y;
        acc[6] += ex * f3.x; acc[7] += ex * f3.y;
        den += ex;
    }
    #pragma unroll
    for (int msk = 8; msk <= 16; msk <<= 1) {
        #pragma unroll
        for (int k = 0; k < 8; ++k)
            acc[k] += __shfl_xor_sync(0xffffffffu, acc[k], msk);
        den += __shfl_xor_sync(0xffffffffu, den, msk);
    }
    if (q == 0) {
        float inv = (end > beg) ? 1.f / den : 0.f;
        #pragma unroll
        for (int k = 0; k < 8; ++k) {
            float v = acc[k] * inv;
            acc[k] = (v > 0.f) ? v : expm1f(v);
        }
        float* orow = out + (size_t)node * FA + fl * 8;
        *(float4*)(orow)     = make_float4(acc[0], acc[1], acc[2], acc[3]);
        *(float4*)(orow + 4) = make_float4(acc[4], acc[5], acc[6], acc[7]);
    }
}

// ---------------- launcher -------------------------------------------------------
extern "C" void kernel_launch(void* const* d_in, const int* in_sizes, int n_in,
                              void* d_out, int out_size) {
    const float* d_sim     = (const float*)d_in[0];
    const float* m_sim     = (const float*)d_in[1];
    const float* Wd        = (const float*)d_in[2];
    const float* Wm        = (const float*)d_in[3];
    const float* Wa        = (const float*)d_in[4];
    const int*   node_type = (const int*)d_in[5];
    const int*   edge_src  = (const int*)d_in[6];
    const int*   edge_dst  = (const int*)d_in[7];
    float* out = (float*)d_out;

    static cudaStream_t s2 = nullptr;
    static cudaEvent_t evFork = nullptr, evScat = nullptr;
    if (!s2) {
        cudaStreamCreateWithFlags(&s2, cudaStreamNonBlocking);
        cudaEventCreateWithFlags(&evFork, cudaEventDisableTiming);
        cudaEventCreateWithFlags(&evScat, cudaEventDisableTiming);
        cudaFuncSetAttribute(k_gemm_mma, cudaFuncAttributeMaxDynamicSharedMemorySize,
                             SMEM_FLOATS * 4);
    }

    const int gemm_blocks = (NN + 127) / 128 + 1;

    cudaEventRecord(evFork, 0);
    cudaStreamWaitEvent(s2, evFork, 0);

    // stream0 (node side): W convert -> sort -> GEMM (s1/s2 fused in epilogue)
    k_wcvt     <<<(2 * FA * DF + 255) / 256, 256>>>(Wd, Wm);
    k_nt_bsum  <<<SBLK, 1024>>>(node_type);
    k_nt_mid   <<<1, 32>>>();
    k_nt_write <<<SBLK, 1024>>>(node_type);

    // s2 (edge side): hist -> CSR offsets -> src-only scatter, all gemm-independent
    k_hist     <<<(NE / 4 + 255) / 256, 256, 0, s2>>>(edge_dst);
    k_cnt_bsum <<<SBLK, 1024, 0, s2>>>();
    k_cnt_mid  <<<1, 32, 0, s2>>>();
    k_cnt_write<<<SBLK, 1024, 0, s2>>>();
    k_scatter  <<<(NE / 2 + 255) / 256, 256, 0, s2>>>(edge_src, edge_dst);
    cudaEventRecord(evScat, s2);

    k_gemm_mma <<<gemm_blocks, 256, SMEM_FLOATS * 4>>>(d_sim, m_sim, Wa);

    cudaStreamWaitEvent(0, evScat, 0);
    k_agg      <<<(NN * 32 + 255) / 256, 256>>>(out);
}

// round 16
// speedup vs baseline: 1.2303x; 1.0186x over previous
#include <cuda_runtime.h>
#include <cuda_fp16.h>
#include <math.h>
#include <stdint.h>

#define NN 50000
#define NE 1000000
#define DF 512
#define FA 64
#define SLOPE 0.2f

#define N4 (NN / 4)
#define SBLK 13                 // 13 * 1024 int4 >= N4; all 13 blocks co-resident

// ---------------- scratch (device globals) ----------------------------------
__device__ uint2 g_zh[NN * 16];          // z as half2 pairs
__device__ float g_s1[NN];
__device__ float g_s2[NN];
__device__ __align__(16) int g_cnt[NN];      // zero at entry; re-zeroed in cnt scan
__device__ __align__(16) int g_off[NN + 4];
__device__ __align__(16) int g_cur[NN + 4];
__device__ int   g_srcs[NE];
__device__ int   g_perm[NN];
__device__ int   g_pc[2];
__device__ volatile int g_stn[SBLK];     // lookback states: 0 = pending, else sum+1
__device__ volatile int g_stc[SBLK];     // (reset by k_agg each replay)
__device__ __align__(16) uint32_t g_wcvt[2 * FA * DF];

// ---------------- helpers -----------------------------------------------------
__device__ __forceinline__ uint32_t smem_u32(const void* p) {
    uint32_t a;
    asm("{ .reg .u64 t; cvta.to.shared.u64 t, %1; cvt.u32.u64 %0, t; }" : "=r"(a) : "l"(p));
    return a;
}
__device__ __forceinline__ void cp16(uint32_t dst, const void* src) {
    asm volatile("cp.async.cg.shared.global [%0], [%1], 16;" :: "r"(dst), "l"(src));
}
#define CP_COMMIT() asm volatile("cp.async.commit_group;" ::: "memory")
#define CP_WAIT(n)  asm volatile("cp.async.wait_group %0;" :: "n"(n) : "memory")

__device__ __forceinline__ uint32_t tf32c(float x) {
    uint32_t r;
    asm("cvt.rna.tf32.f32 %0, %1;" : "=r"(r) : "f"(x));
    return r;
}
__device__ __forceinline__ uint32_t pack_h2(float lo, float hi) {
    __half2 h = __floats2half2_rn(lo, hi);
    return *reinterpret_cast<uint32_t*>(&h);
}
__device__ __forceinline__ void mma_tf32(float4& d, uint32_t a0, uint32_t a1,
                                         uint32_t a2, uint32_t a3,
                                         uint32_t b0, uint32_t b1) {
    asm volatile(
        "mma.sync.aligned.m16n8k8.row.col.f32.tf32.tf32.f32 "
        "{%0,%1,%2,%3}, {%4,%5,%6,%7}, {%8,%9}, {%0,%1,%2,%3};"
        : "+f"(d.x), "+f"(d.y), "+f"(d.z), "+f"(d.w)
        : "r"(a0), "r"(a1), "r"(a2), "r"(a3), "r"(b0), "r"(b1));
}

__device__ __forceinline__ int block_exscan(int s, int lane, int wid,
                                            int* ws, int* tot) {
    int x = s;
    #pragma unroll
    for (int o = 1; o < 32; o <<= 1) {
        int tt = __shfl_up_sync(0xffffffffu, x, o);
        if (lane >= o) x += tt;
    }
    if (lane == 31) ws[wid] = x;
    __syncthreads();
    if (wid == 0) {
        int y = ws[lane];
        #pragma unroll
        for (int o = 1; o < 32; o <<= 1) {
            int tt = __shfl_up_sync(0xffffffffu, y, o);
            if (lane >= o) y += tt;
        }
        ws[lane] = y;
    }
    __syncthreads();
    *tot = ws[31];
    return (wid ? ws[wid - 1] : 0) + x - s;
}

// Decoupled-lookback prefix: publish own total, spin-sum lower blocks.
// Safe: all SBLK=13 blocks are co-resident (<< 148 SMs).
__device__ __forceinline__ int lookback_prefix(volatile int* st, int b, int tot,
                                               int* sh_run) {
    if (threadIdx.x == 0) {
        st[b] = tot + 1;
        __threadfence();
        int run = 0;
        for (int i = 0; i < b; ++i) {
            int v;
            do { v = st[i]; } while (v == 0);
            run += v - 1;
        }
        *sh_run = run;
    }
    __syncthreads();
    return *sh_run;
}

// ---------------- K1: nt lookback scan + stable partition + W convert ----------
__global__ __launch_bounds__(1024) void k_nt_scan(
    const int* __restrict__ nt,
    const float* __restrict__ Wd, const float* __restrict__ Wm) {
    __shared__ int ws[32];
    __shared__ int sh_run;
    const int b = blockIdx.x;
    int idx = b * 1024 + threadIdx.x;
    int4 v = make_int4(0, 0, 0, 0);
    if (idx < N4) v = ((const int4*)nt)[idx];
    int s = v.x + v.y + v.z + v.w;
    int lane = threadIdx.x & 31, wid = threadIdx.x >> 5;
    int tot;
    int ex = block_exscan(s, lane, wid, ws, &tot);
    int run = lookback_prefix(g_stn, b, tot, &sh_run);

    if (idx < N4) {
        int p1 = run + ex;
        int i0 = idx * 4;
        if (v.x) g_perm[p1++] = i0;     else g_perm[NN - 1 - (i0     - p1)] = i0;
        if (v.y) g_perm[p1++] = i0 + 1; else g_perm[NN - 1 - (i0 + 1 - p1)] = i0 + 1;
        if (v.z) g_perm[p1++] = i0 + 2; else g_perm[NN - 1 - (i0 + 2 - p1)] = i0 + 2;
        if (v.w) g_perm[p1++] = i0 + 3; else g_perm[NN - 1 - (i0 + 3 - p1)] = i0 + 3;
    }
    if (b == SBLK - 1 && threadIdx.x == 0) {
        g_pc[0] = run + tot;
        g_pc[1] = NN - (run + tot);
    }
    // fused W pre-convert (13312 threads x 5 elements covers 65536)
    for (int i = b * 1024 + threadIdx.x; i < 2 * FA * DF; i += SBLK * 1024) {
        float w = (i < FA * DF) ? Wd[i] : Wm[i - FA * DF];
        g_wcvt[i] = tf32c(w);
    }
}

// ---------------- K2: dst histogram ---------------------------------------------
__global__ void k_hist(const int* __restrict__ dst) {
    int i = blockIdx.x * blockDim.x + threadIdx.x;
    if (i < NE / 4) {
        int4 d = ((const int4*)dst)[i];
        atomicAdd(&g_cnt[d.x], 1);
        atomicAdd(&g_cnt[d.y], 1);
        atomicAdd(&g_cnt[d.z], 1);
        atomicAdd(&g_cnt[d.w], 1);
    }
}

// ---------------- K3: cnt lookback scan -> CSR offsets; re-zeros g_cnt ----------
__global__ __launch_bounds__(1024) void k_cnt_scan() {
    __shared__ int ws[32];
    __shared__ int sh_run;
    const int b = blockIdx.x;
    int idx = b * 1024 + threadIdx.x;
    int4* cnt4 = (int4*)g_cnt;
    int4 v = make_int4(0, 0, 0, 0);
    if (idx < N4) {
        v = cnt4[idx];
        cnt4[idx] = make_int4(0, 0, 0, 0);      // restore zeros for next replay
    }
    int s = v.x + v.y + v.z + v.w;
    int lane = threadIdx.x & 31, wid = threadIdx.x >> 5;
    int tot;
    int ex = block_exscan(s, lane, wid, ws, &tot);
    int run = lookback_prefix(g_stc, b, tot, &sh_run);

    if (idx < N4) {
        int excl = run + ex;
        int4 o;
        o.x = excl;
        o.y = excl + v.x;
        o.z = o.y + v.y;
        o.w = o.z + v.z;
        ((int4*)g_off)[idx] = o;
        ((int4*)g_cur)[idx] = o;
    }
    if (b == 0 && threadIdx.x == 0) g_off[NN] = NE;
}

// ---------------- K4: tf32 mma.sync GEMM (fused s1/s2 epilogue) -----------------
#define KC 32
#define PAD 36
#define A_FLOATS (128 * PAD)
#define B_FLOATS (64 * PAD)
#define SMEM_FLOATS (2 * A_FLOATS + 2 * B_FLOATS)
#define NCHUNK (DF / KC)

__global__ __launch_bounds__(256) void k_gemm_mma(
    const float* __restrict__ d_sim, const float* __restrict__ m_sim,
    const float* __restrict__ Wa)
{
    extern __shared__ float dsm[];
    __shared__ int ns[128];

    const int tid  = threadIdx.x;
    const int wid  = tid >> 5;
    const int lane = tid & 31;
    const int g    = lane >> 2;
    const int t    = lane & 3;

    const int c1 = g_pc[0];
    const int tiles_d = (c1 + 127) >> 7;
    const int b = blockIdx.x;

    const float* X; const uint32_t* W; int off, cnt;
    if (b < tiles_d) {
        X = d_sim; W = g_wcvt; off = b * 128; cnt = min(128, c1 - b * 128);
    } else {
        int c0 = NN - c1;
        int b2 = b - tiles_d;
        cnt = min(128, c0 - b2 * 128);
        if (cnt <= 0) return;
        X = m_sim; W = g_wcvt + FA * DF; off = c1 + b2 * 128;
    }

    if (tid < 128) ns[tid] = g_perm[off + min(tid, cnt - 1)];
    __syncthreads();

    const uint32_t smb = smem_u32(dsm);

    auto load_chunk = [&](int buf, int kt) {
        uint32_t bA = smb + buf * A_FLOATS * 4;
        uint32_t bB = smb + (2 * A_FLOATS + buf * B_FLOATS) * 4;
        #pragma unroll
        for (int i = 0; i < 4; ++i) {
            int s = i * 256 + tid;
            int row = s >> 3, q = s & 7;
            cp16(bA + (row * PAD + q * 4) * 4, X + (size_t)ns[row] * DF + kt + q * 4);
        }
        #pragma unroll
        for (int i = 0; i < 2; ++i) {
            int s = i * 256 + tid;
            int row = s >> 3, q = s & 7;
            cp16(bB + (row * PAD + q * 4) * 4, W + (size_t)row * DF + kt + q * 4);
        }
    };

    float4 acc[8];
    #pragma unroll
    for (int j = 0; j < 8; ++j) acc[j] = make_float4(0.f, 0.f, 0.f, 0.f);

    load_chunk(0, 0);
    CP_COMMIT();

    const int m0 = wid * 16;
    for (int c = 0; c < NCHUNK; ++c) {
        if (c + 1 < NCHUNK) {
            load_chunk((c + 1) & 1, (c + 1) * KC);
            CP_COMMIT();
            CP_WAIT(1);
        } else {
            CP_WAIT(0);
        }
        __syncthreads();

        const float*    As = dsm + (c & 1) * A_FLOATS;
        const uint32_t* Bs = (const uint32_t*)(dsm + 2 * A_FLOATS + (c & 1) * B_FLOATS);

        #pragma unroll
        for (int ks = 0; ks < 4; ++ks) {
            const int k0 = ks * 8;
            uint32_t a0 = tf32c(As[(m0 + g)     * PAD + k0 + t]);
            uint32_t a1 = tf32c(As[(m0 + g + 8) * PAD + k0 + t]);
            uint32_t a2 = tf32c(As[(m0 + g)     * PAD + k0 + t + 4]);
            uint32_t a3 = tf32c(As[(m0 + g + 8) * PAD + k0 + t + 4]);
            #pragma unroll
            for (int j = 0; j < 8; ++j) {
                uint32_t b0 = Bs[(8 * j + g) * PAD + k0 + t];
                uint32_t b1 = Bs[(8 * j + g) * PAD + k0 + t + 4];
                mma_tf32(acc[j], a0, a1, a2, a3, b0, b1);
            }
        }
        __syncthreads();
    }

    // ---- epilogue: z rows as half2 + fused s1/s2 ------------------------------
    const int r0 = m0 + g;
    const int r1 = r0 + 8;
    const bool v0 = r0 < cnt, v1 = r1 < cnt;
    float s1a = 0.f, s2a = 0.f, s1b = 0.f, s2b = 0.f;
    int node0 = ns[r0];
    int node1 = ns[r1];
    uint32_t* z0 = (uint32_t*)g_zh + (size_t)node0 * 32;
    uint32_t* z1 = (uint32_t*)g_zh + (size_t)node1 * 32;
    #pragma unroll
    for (int j = 0; j < 8; ++j) {
        int n0 = 8 * j + 2 * t;
        float wa1x = Wa[n0], wa1y = Wa[n0 + 1];
        float wa2x = Wa[FA + n0], wa2y = Wa[FA + n0 + 1];
        if (v0) z0[4 * j + t] = pack_h2(acc[j].x, acc[j].y);
        s1a += acc[j].x * wa1x + acc[j].y * wa1y;
        s2a += acc[j].x * wa2x + acc[j].y * wa2y;
        if (v1) z1[4 * j + t] = pack_h2(acc[j].z, acc[j].w);
        s1b += acc[j].z * wa1x + acc[j].w * wa1y;
        s2b += acc[j].z * wa2x + acc[j].w * wa2y;
    }
    #pragma unroll
    for (int msk = 1; msk <= 2; msk <<= 1) {
        s1a += __shfl_xor_sync(0xffffffffu, s1a, msk);
        s2a += __shfl_xor_sync(0xffffffffu, s2a, msk);
        s1b += __shfl_xor_sync(0xffffffffu, s1b, msk);
        s2b += __shfl_xor_sync(0xffffffffu, s2b, msk);
    }
    if (t == 0) {
        if (v0) { g_s1[node0] = s1a; g_s2[node0] = s2a; }
        if (v1) { g_s1[node1] = s1b; g_s2[node1] = s2b; }
    }
}

// ---------------- K5: src-only CSR scatter (no score dependency) ----------------
__global__ void k_scatter(const int* __restrict__ src, const int* __restrict__ dst) {
    int i = blockIdx.x * blockDim.x + threadIdx.x;
    if (i >= NE / 2) return;
    int2 ss = ((const int2*)src)[i];
    int2 dd = ((const int2*)dst)[i];
    g_srcs[atomicAdd(&g_cur[dd.x], 1)] = ss.x;
    g_srcs[atomicAdd(&g_cur[dd.y], 1)] = ss.y;
}

// ---------------- K6: inline logits + softmax aggregation + elu -----------------
// Warp-uniform loop so the intra-loop shfl has all lanes present.
// Also resets the lookback state arrays for the next graph replay.
__global__ void k_agg(float* __restrict__ out) {
    int gtid = blockIdx.x * blockDim.x + threadIdx.x;
    if (gtid < SBLK) { g_stn[gtid] = 0; g_stc[gtid] = 0; }
    int node = gtid >> 5;
    int lane = threadIdx.x & 31;
    if (node >= NN) return;
    int beg = g_off[node], end = g_off[node + 1];
    int q  = lane >> 3;
    int fl = lane & 7;
    float s2n = g_s2[node];

    float acc[8] = {0.f, 0.f, 0.f, 0.f, 0.f, 0.f, 0.f, 0.f};
    float den = 0.f;
    for (int base = beg; base < end; base += 4) {
        int j = base + q;
        bool valid = j < end;
        int s = g_srcs[valid ? j : beg];
        float ex = 0.f;
        if (fl == 0 && valid) {
            float e = g_s1[s] + s2n;
            e = (e > 0.f) ? e : SLOPE * e;
            ex = __expf(e);
        }
        ex = __shfl_sync(0xffffffffu, ex, lane & 24);
        uint4 zz = ((const uint4*)g_zh)[(size_t)s * 8 + fl];
        float2 f0 = __half22float2(*reinterpret_cast<__half2*>(&zz.x));
        float2 f1 = __half22float2(*reinterpret_cast<__half2*>(&zz.y));
        float2 f2 = __half22float2(*reinterpret_cast<__half2*>(&zz.z));
        float2 f3 = __half22float2(*reinterpret_cast<__half2*>(&zz.w));
        acc[0] += ex * f0.x; acc[1] += ex * f0.y;
        acc[2] += ex * f1.x; acc[3] += ex * f1.y;
        acc[4] += ex * f2.x; acc[5] += ex * f2.y;
        acc[6] += ex * f3.x; acc[7] += ex * f3.y;
        den += ex;
    }
    #pragma unroll
    for (int msk = 8; msk <= 16; msk <<= 1) {
        #pragma unroll
        for (int k = 0; k < 8; ++k)
            acc[k] += __shfl_xor_sync(0xffffffffu, acc[k], msk);
        den += __shfl_xor_sync(0xffffffffu, den, msk);
    }
    if (q == 0) {
        float inv = (end > beg) ? 1.f / den : 0.f;
        #pragma unroll
        for (int k = 0; k < 8; ++k) {
            float v = acc[k] * inv;
            acc[k] = (v > 0.f) ? v : expm1f(v);
        }
        float* orow = out + (size_t)node * FA + fl * 8;
        *(float4*)(orow)     = make_float4(acc[0], acc[1], acc[2], acc[3]);
        *(float4*)(orow + 4) = make_float4(acc[4], acc[5], acc[6], acc[7]);
    }
}

// ---------------- launcher -------------------------------------------------------
extern "C" void kernel_launch(void* const* d_in, const int* in_sizes, int n_in,
                              void* d_out, int out_size) {
    const float* d_sim     = (const float*)d_in[0];
    const float* m_sim     = (const float*)d_in[1];
    const float* Wd        = (const float*)d_in[2];
    const float* Wm        = (const float*)d_in[3];
    const float* Wa        = (const float*)d_in[4];
    const int*   node_type = (const int*)d_in[5];
    const int*   edge_src  = (const int*)d_in[6];
    const int*   edge_dst  = (const int*)d_in[7];
    float* out = (float*)d_out;

    static cudaStream_t s2 = nullptr;
    static cudaEvent_t evFork = nullptr, evScat = nullptr;
    if (!s2) {
        cudaStreamCreateWithFlags(&s2, cudaStreamNonBlocking);
        cudaEventCreateWithFlags(&evFork, cudaEventDisableTiming);
        cudaEventCreateWithFlags(&evScat, cudaEventDisableTiming);
        cudaFuncSetAttribute(k_gemm_mma, cudaFuncAttributeMaxDynamicSharedMemorySize,
                             SMEM_FLOATS * 4);
    }

    const int gemm_blocks = (NN + 127) / 128 + 1;

    cudaEventRecord(evFork, 0);
    cudaStreamWaitEvent(s2, evFork, 0);

    // stream0 (node side): nt lookback scan (+W convert) -> GEMM
    k_nt_scan <<<SBLK, 1024>>>(node_type, Wd, Wm);

    // s2 (edge side): hist -> cnt lookback scan -> src-only scatter
    k_hist    <<<(NE / 4 + 255) / 256, 256, 0, s2>>>(edge_dst);
    k_cnt_scan<<<SBLK, 1024, 0, s2>>>();
    k_scatter <<<(NE / 2 + 255) / 256, 256, 0, s2>>>(edge_src, edge_dst);
    cudaEventRecord(evScat, s2);

    k_gemm_mma<<<gemm_blocks, 256, SMEM_FLOATS * 4>>>(d_sim, m_sim, Wa);

    cudaStreamWaitEvent(0, evScat, 0);
    k_agg     <<<(NN * 32 + 255) / 256, 256>>>(out);
}